// round 1
// baseline (speedup 1.0000x reference)
#include <cuda_runtime.h>

#define NT 256
#define SMEM_FLOATS (7776*2 + 1296*3 + 32 + 12 + 32)
#define SMEM_BYTES  (SMEM_FLOATS * 4)

// ---------------------------------------------------------------------------
// helpers
// ---------------------------------------------------------------------------

__device__ __forceinline__ float block_reduce_sum(float v, float* sRed, int tid)
{
    #pragma unroll
    for (int o = 16; o > 0; o >>= 1) v += __shfl_down_sync(0xffffffffu, v, o);
    if ((tid & 31) == 0) sRed[tid >> 5] = v;
    __syncthreads();
    if (tid < 32) {
        float w = (tid < (NT >> 5)) ? sRed[tid] : 0.0f;
        #pragma unroll
        for (int o = 4; o > 0; o >>= 1) w += __shfl_down_sync(0xffffffffu, w, o);
        if (tid == 0) sRed[0] = w;
    }
    __syncthreads();
    float r = sRed[0];
    __syncthreads();
    return r;
}

// node = x0 * P[slice] + x1 * P[1296 + slice], arbitrary 3-dim slice
__device__ __forceinline__ void load_node(float* __restrict__ sN,
                                          const float* __restrict__ P,
                                          float x0, float x1,
                                          int ca, int cb, int cc,
                                          int sa, int sb, int sc, int tid)
{
    const int n = ca * cb * cc;
    for (int k = tid; k < n; k += NT) {
        int a   = k / (cb * cc);
        int rem = k - a * (cb * cc);
        int bb  = rem / cc;
        int c   = rem - bb * cc;
        int addr = a * sa + bb * sb + c * sc;
        sN[k] = x0 * P[addr] + x1 * P[addr + 1296];
    }
}

// out[(A*6+p)*6+q] = sum_x in[A*6+x] * sN[(swap ? p*6+q : q*6+p)*6 + x]
__device__ __forceinline__ void rowstep(float* __restrict__ out,
                                        const float* __restrict__ in,
                                        const float* __restrict__ sN,
                                        int As, bool swap, int tid)
{
    const int n = As * 36;
    for (int k = tid; k < n; k += NT) {
        int A = k / 36;
        int p = (k / 6) % 6;
        int q = k % 6;
        int nb = (swap ? (p * 6 + q) : (q * 6 + p)) * 6;
        float acc = 0.0f;
        #pragma unroll
        for (int x = 0; x < 6; x++) acc += in[A * 6 + x] * sN[nb + x];
        out[k] = acc;
    }
}

// out[A*6+p] = sum_x in[A*6+x] * sN[p*6+x]   (A in [0,216))
__device__ __forceinline__ void laststep(float* __restrict__ out,
                                         const float* __restrict__ in,
                                         const float* __restrict__ sN, int tid)
{
    for (int k = tid; k < 1296; k += NT) {
        int A = k / 6;
        int p = k % 6;
        float acc = 0.0f;
        #pragma unroll
        for (int x = 0; x < 6; x++) acc += in[A * 6 + x] * sN[p * 6 + x];
        out[k] = acc;
    }
}

// out[c*36 + d*6 + r] = sum_u E[u*216 + c] * sN[u*36 + r*6 + d]
__device__ __forceinline__ void mpo_first(float* __restrict__ out,
                                          const float* __restrict__ E,
                                          const float* __restrict__ sN, int tid)
{
    for (int k = tid; k < 7776; k += NT) {
        int c = k / 36;
        int d = (k / 6) % 6;
        int r = k % 6;
        float acc = 0.0f;
        #pragma unroll
        for (int u = 0; u < 6; u++) acc += E[u * 216 + c] * sN[u * 36 + r * 6 + d];
        out[k] = acc;
    }
}

// out[c*36 + d*6 + r] = sum_{u,x} in[u*1296 + c*6 + x] * sN[u*216 + r*36 + d*6 + x]
__device__ __forceinline__ void mpo_full(float* __restrict__ out,
                                         const float* __restrict__ in,
                                         const float* __restrict__ sN, int tid)
{
    for (int c = tid; c < 216; c += NT) {
        float s[36];
        #pragma unroll
        for (int u = 0; u < 6; u++)
            #pragma unroll
            for (int x = 0; x < 6; x++) s[u * 6 + x] = in[u * 1296 + c * 6 + x];
        for (int dr = 0; dr < 36; dr++) {
            int d = dr / 6;
            int r = dr % 6;
            float acc = 0.0f;
            #pragma unroll
            for (int u = 0; u < 6; u++)
                #pragma unroll
                for (int x = 0; x < 6; x++)
                    acc += s[u * 6 + x] * sN[u * 216 + r * 36 + d * 6 + x];
            out[c * 36 + dr] = acc;
        }
    }
}

// out[c*6 + d] = sum_{u,x} in[u*1296 + c*6 + x] * sN[u*36 + d*6 + x]
__device__ __forceinline__ void mpo_last(float* __restrict__ out,
                                         const float* __restrict__ in,
                                         const float* __restrict__ sN, int tid)
{
    for (int k = tid; k < 1296; k += NT) {
        int c = k / 6;
        int d = k % 6;
        float acc = 0.0f;
        #pragma unroll
        for (int u = 0; u < 6; u++)
            #pragma unroll
            for (int x = 0; x < 6; x++)
                acc += in[u * 1296 + c * 6 + x] * sN[u * 36 + d * 6 + x];
        out[k] = acc;
    }
}

// R[m*36 + d2*6 + l3] = sum_{d3} Eb[(m%36)*36 + d2*6 + d3] * sN[(m/36)*36 + d3*6 + l3]
// with m = (u3, d0, d1) and Eb flat [d0][d1][d2][d3]
__device__ __forceinline__ void rstep(float* __restrict__ out,
                                      const float* __restrict__ Eb,
                                      const float* __restrict__ sN, int tid)
{
    for (int k = tid; k < 7776; k += NT) {
        int m    = k / 36;
        int d2   = (k / 6) % 6;
        int l3   = k % 6;
        int u3   = m / 36;
        int d0d1 = m % 36;
        float acc = 0.0f;
        #pragma unroll
        for (int d3 = 0; d3 < 6; d3++)
            acc += Eb[d0d1 * 36 + d2 * 6 + d3] * sN[u3 * 36 + d3 * 6 + l3];
        out[k] = acc;
    }
}

// T[u*216 + r*36 + d*6 + l] = sum_m L[u*1296 + m*6 + l] * R[m*36 + d*6 + r]
__device__ __forceinline__ void tgemm(float* __restrict__ T,
                                      const float* __restrict__ L,
                                      const float* __restrict__ R, int tid)
{
    for (int k = tid; k < 1296; k += NT) {
        int u = k / 216;
        int r = (k / 36) % 6;
        int d = (k / 6) % 6;
        int l = k % 6;
        float acc = 0.0f;
        #pragma unroll 6
        for (int m = 0; m < 216; m++)
            acc += L[u * 1296 + m * 6 + l] * R[m * 36 + d * 6 + r];
        T[k] = acc;
    }
}

__device__ __forceinline__ void unit_norm(float* __restrict__ dst,
                                          const float* __restrict__ src,
                                          int n, float* sRed, int tid)
{
    float v = 0.0f;
    for (int k = tid; k < n; k += NT) { float t = src[k]; v += t * t; }
    float ss = block_reduce_sum(v, sRed, tid);
    float sc = rsqrtf(ss);
    for (int k = tid; k < n; k += NT) dst[k] = src[k] * sc;
    __syncthreads();
}

// ---------------------------------------------------------------------------
// kernel: one block per batch element
// ---------------------------------------------------------------------------

__global__ __launch_bounds__(NT, 2)
void peps_forward_kernel(const float* __restrict__ inputs,
                         const float* __restrict__ peps,
                         const float* __restrict__ pepsc,
                         float* __restrict__ out, int B)
{
    extern __shared__ float sm[];
    float* sA   = sm;              // 7776
    float* sB   = sA + 7776;       // 7776
    float* sE   = sB + 7776;       // 1296  (env_top / T)
    float* sEb  = sE + 1296;       // 1296  (env_bot)
    float* sN   = sEb + 1296;      // 1296  (node buffer)
    float* sRed = sN + 1296;       // 32
    float* sOut = sRed + 32;       // 12
    float* sX   = sOut + 12;       // 32

    const int tid = threadIdx.x;
    const int b = blockIdx.x;
    if (b >= B) return;

    if (tid < 32) sX[tid] = inputs[b * 32 + tid];
    __syncthreads();

    #define PB(i, j) (peps + ((i) * 4 + (j)) * 2 * 1296)
    #define XX0(i, j) sX[((i) * 4 + (j)) * 2]
    #define XX1(i, j) sX[((i) * 4 + (j)) * 2 + 1]

    // ================= Row 0 (top boundary, u=0) =================
    // n00: u=0, l=0 -> [r][d]
    load_node(sN, PB(0, 0), XX0(0, 0), XX1(0, 0), 6, 6, 1, 36, 6, 0, tid);
    __syncthreads();
    for (int k = tid; k < 36; k += NT) { int d0 = k / 6, r = k % 6; sA[k] = sN[r * 6 + d0]; }
    __syncthreads();
    // n01: u=0 -> [r][d][x]
    load_node(sN, PB(0, 1), XX0(0, 1), XX1(0, 1), 6, 6, 6, 36, 6, 1, tid);
    __syncthreads();
    rowstep(sB, sA, sN, 6, false, tid);
    __syncthreads();
    load_node(sN, PB(0, 2), XX0(0, 2), XX1(0, 2), 6, 6, 6, 36, 6, 1, tid);
    __syncthreads();
    rowstep(sA, sB, sN, 36, false, tid);
    __syncthreads();
    // n03: u=0, r=0 -> [d][x]
    load_node(sN, PB(0, 3), XX0(0, 3), XX1(0, 3), 6, 6, 1, 6, 1, 0, tid);
    __syncthreads();
    laststep(sB, sA, sN, tid);
    __syncthreads();
    unit_norm(sE, sB, 1296, sRed, tid);   // env (row 0), unit

    // ================= Row 1 (MPO) =================
    // n10: l=0 -> [u][r][d]
    load_node(sN, PB(1, 0), XX0(1, 0), XX1(1, 0), 6, 6, 6, 216, 36, 6, tid);
    __syncthreads();
    mpo_first(sA, sE, sN, tid);
    __syncthreads();
    load_node(sN, PB(1, 1), XX0(1, 1), XX1(1, 1), 6, 6, 36, 216, 36, 1, tid); // full
    __syncthreads();
    mpo_full(sB, sA, sN, tid);
    __syncthreads();
    load_node(sN, PB(1, 2), XX0(1, 2), XX1(1, 2), 6, 6, 36, 216, 36, 1, tid); // full
    __syncthreads();
    mpo_full(sA, sB, sN, tid);
    __syncthreads();
    // n13: r=0 -> [u][d][x]
    load_node(sN, PB(1, 3), XX0(1, 3), XX1(1, 3), 6, 6, 6, 216, 6, 1, tid);
    __syncthreads();
    mpo_last(sB, sA, sN, tid);
    __syncthreads();
    unit_norm(sE, sB, 1296, sRed, tid);   // env_top, unit

    // ================= Row 3 (bottom boundary, d=0) =================
    // n30: d=0, l=0 -> [u][r]
    load_node(sN, PB(3, 0), XX0(3, 0), XX1(3, 0), 6, 6, 1, 216, 36, 0, tid);
    __syncthreads();
    for (int k = tid; k < 36; k += NT) sA[k] = sN[k];
    __syncthreads();
    // n31: d=0 -> [u][r][x]
    load_node(sN, PB(3, 1), XX0(3, 1), XX1(3, 1), 6, 6, 6, 216, 36, 1, tid);
    __syncthreads();
    rowstep(sB, sA, sN, 6, true, tid);
    __syncthreads();
    load_node(sN, PB(3, 2), XX0(3, 2), XX1(3, 2), 6, 6, 6, 216, 36, 1, tid);
    __syncthreads();
    rowstep(sA, sB, sN, 36, true, tid);
    __syncthreads();
    // n33: r=0, d=0 -> [u][x]
    load_node(sN, PB(3, 3), XX0(3, 3), XX1(3, 3), 6, 6, 1, 216, 1, 0, tid);
    __syncthreads();
    laststep(sB, sA, sN, tid);
    __syncthreads();
    unit_norm(sEb, sB, 1296, sRed, tid);  // env_bot, unit

    // ================= Row 2 (center row) =================
    // L1: n20 l=0 -> [u][r][d]
    load_node(sN, PB(2, 0), XX0(2, 0), XX1(2, 0), 6, 6, 6, 216, 36, 6, tid);
    __syncthreads();
    mpo_first(sA, sE, sN, tid);           // L1 in sA
    __syncthreads();
    load_node(sN, PB(2, 1), XX0(2, 1), XX1(2, 1), 6, 6, 36, 216, 36, 1, tid); // full
    __syncthreads();
    mpo_full(sB, sA, sN, tid);            // L2 in sB  [u2][u3][d0][d1][l2]
    __syncthreads();
    // n23: r=0 -> [u][d][l]
    load_node(sN, PB(2, 3), XX0(2, 3), XX1(2, 3), 6, 6, 6, 216, 6, 1, tid);
    __syncthreads();
    rstep(sA, sEb, sN, tid);              // R in sA   [u3,d0,d1][d2][l3]
    __syncthreads();
    tgemm(sE, sB, sA, tid);               // T in sE   [u][r][d][l] (center leg order)
    __syncthreads();

    // ================= Final contraction with peps_center =================
    const float xc0 = sX[(2 * 4 + 2) * 2];
    const float xc1 = sX[(2 * 4 + 2) * 2 + 1];
    for (int o = 0; o < 10; o++) {
        float v = 0.0f;
        const float* p0 = pepsc + o * 1296;
        const float* p1 = pepsc + 12960 + o * 1296;
        for (int k = tid; k < 1296; k += NT)
            v += sE[k] * (xc0 * p0[k] + xc1 * p1[k]);
        float s = block_reduce_sum(v, sRed, tid);
        if (tid == 0) sOut[o] = s;
        __syncthreads();
    }

    if (tid < 10) {
        float nrm = 0.0f;
        #pragma unroll
        for (int o = 0; o < 10; o++) { float t = sOut[o]; nrm += t * t; }
        out[b * 10 + tid] = sOut[tid] * rsqrtf(nrm);
    }
}

// ---------------------------------------------------------------------------
// launch
// ---------------------------------------------------------------------------

extern "C" void kernel_launch(void* const* d_in, const int* in_sizes, int n_in,
                              void* d_out, int out_size)
{
    const float* inputs = (const float*)d_in[0];   // (B,4,4,2)
    const float* peps   = (const float*)d_in[1];   // (4,4,2,6,6,6,6)
    const float* pepsc  = (const float*)d_in[2];   // (2,10,6,6,6,6)
    float* out = (float*)d_out;                    // (B,10)

    const int B = in_sizes[0] / 32;

    cudaFuncSetAttribute(peps_forward_kernel,
                         cudaFuncAttributeMaxDynamicSharedMemorySize, SMEM_BYTES);
    peps_forward_kernel<<<B, NT, SMEM_BYTES>>>(inputs, peps, pepsc, out, B);
}

// round 2
// speedup vs baseline: 1.5283x; 1.5283x over previous
#include <cuda_runtime.h>

#define NT 256

// shared-memory layout (float offsets)
#define OFF_A    0        // 7776  scratch A / L1 / R / row0+row3 ping-pong
#define OFF_B    7776     // 7776  scratch B / L2
#define OFF_N    15552    // 1296  node buffer
#define OFF_E    16848    // 1296  env0 / env_top / env_botT / T
#define OFF_RED  18144    // 32
#define OFF_OUT  18176    // 16
#define OFF_X    18192    // 32
#define SMEM_FLOATS 18224
#define SMEM_BYTES  (SMEM_FLOATS * 4)

extern __shared__ float sm[];

// ---------------------------------------------------------------------------
// reductions
// ---------------------------------------------------------------------------

__device__ __forceinline__ float block_reduce_sum(float v, int tid)
{
    float* sRed = sm + OFF_RED;
    #pragma unroll
    for (int o = 16; o > 0; o >>= 1) v += __shfl_down_sync(0xffffffffu, v, o);
    if ((tid & 31) == 0) sRed[tid >> 5] = v;
    __syncthreads();
    if (tid < 32) {
        float w = (tid < (NT >> 5)) ? sRed[tid] : 0.0f;
        #pragma unroll
        for (int o = 4; o > 0; o >>= 1) w += __shfl_down_sync(0xffffffffu, w, o);
        if (tid == 0) sRed[0] = w;
    }
    __syncthreads();
    float r = sRed[0];
    __syncthreads();
    return r;
}

__device__ __forceinline__ void unit_norm(int dstOff, int srcOff, int n, int tid)
{
    float v = 0.0f;
    for (int k = tid; k < n; k += NT) { float t = sm[srcOff + k]; v += t * t; }
    float sc = rsqrtf(block_reduce_sum(v, tid));
    for (int k = tid; k < n; k += NT) sm[dstOff + k] = sm[srcOff + k] * sc;
    __syncthreads();
}

// env_bot, transposed:  dst[d3*216 + d0d1*6 + d2] = src[d0d1*36 + d2*6 + d3] * sc
__device__ __forceinline__ void unit_norm_T(int dstOff, int srcOff, int tid)
{
    float v = 0.0f;
    for (int k = tid; k < 1296; k += NT) { float t = sm[srcOff + k]; v += t * t; }
    float sc = rsqrtf(block_reduce_sum(v, tid));
    for (int k = tid; k < 1296; k += NT) {
        int dd = k / 36;
        int d2 = (k / 6) % 6;
        int d3 = k % 6;
        sm[dstOff + d3 * 216 + dd * 6 + d2] = sm[srcOff + k] * sc;
    }
    __syncthreads();
}

// ---------------------------------------------------------------------------
// node loaders (node = x0 * P[slice] + x1 * P[1296 + slice])
// ---------------------------------------------------------------------------

__device__ __forceinline__ void load_node(int nodeOff, const float* __restrict__ P,
                                          float x0, float x1,
                                          int ca, int cb, int cc,
                                          int sa, int sb, int sc, int tid)
{
    const int n = ca * cb * cc;
    for (int k = tid; k < n; k += NT) {
        int a   = k / (cb * cc);
        int rem = k - a * (cb * cc);
        int bb  = rem / cc;
        int c   = rem - bb * cc;
        int addr = a * sa + bb * sb + c * sc;
        sm[nodeOff + k] = x0 * P[addr] + x1 * P[addr + 1296];
    }
}

// full node for mpo_full: nodeL[((u*6+x)*6+d)*6 + r] = n[u][r][d][x]
__device__ __forceinline__ void load_node_full(int nodeOff, const float* __restrict__ P,
                                               float x0, float x1, int tid)
{
    for (int k = tid; k < 1296; k += NT) {
        int u   = k / 216;
        int rem = k % 216;
        int x   = rem / 36;  rem %= 36;
        int d   = rem / 6;
        int r   = rem % 6;
        int addr = u * 216 + r * 36 + d * 6 + x;
        sm[nodeOff + k] = x0 * P[addr] + x1 * P[addr + 1296];
    }
}

// ---------------------------------------------------------------------------
// small-row helpers (rows 0 and 3; tiny work, scalar is fine)
// ---------------------------------------------------------------------------

__device__ __forceinline__ void rowstep(int outOff, int inOff, int nodeOff,
                                        int As, bool swap, int tid)
{
    const int n = As * 36;
    for (int k = tid; k < n; k += NT) {
        int A = k / 36;
        int p = (k / 6) % 6;
        int q = k % 6;
        int nb = (swap ? (p * 6 + q) : (q * 6 + p)) * 6;
        float acc = 0.0f;
        #pragma unroll
        for (int x = 0; x < 6; x++) acc += sm[inOff + A * 6 + x] * sm[nodeOff + nb + x];
        sm[outOff + k] = acc;
    }
}

__device__ __forceinline__ void laststep(int outOff, int inOff, int nodeOff, int tid)
{
    for (int k = tid; k < 1296; k += NT) {
        int A = k / 6;
        int p = k % 6;
        float acc = 0.0f;
        #pragma unroll
        for (int x = 0; x < 6; x++) acc += sm[inOff + A * 6 + x] * sm[nodeOff + p * 6 + x];
        sm[outOff + k] = acc;
    }
}

// ---------------------------------------------------------------------------
// MPO kernels (register acc[36], LDS.128 broadcast node reads)
// ---------------------------------------------------------------------------

// out[c*36 + b] = sum_u E[u*216 + c] * nodeF[u*36 + b]      (b = d*6+r)
__device__ __noinline__ void mpo_first36(int outOff, int eOff, int nodeOff, int tid)
{
    if (tid >= 216) return;
    float acc[36];
    #pragma unroll
    for (int i = 0; i < 36; i++) acc[i] = 0.0f;
    #pragma unroll 1
    for (int u = 0; u < 6; u++) {
        float e = sm[eOff + u * 216 + tid];
        const float4* nb = (const float4*)(sm + nodeOff + u * 36);
        #pragma unroll
        for (int q = 0; q < 9; q++) {
            float4 nv = nb[q];
            acc[q * 4 + 0] += e * nv.x;
            acc[q * 4 + 1] += e * nv.y;
            acc[q * 4 + 2] += e * nv.z;
            acc[q * 4 + 3] += e * nv.w;
        }
    }
    float4* out = (float4*)(sm + outOff + tid * 36);
    #pragma unroll
    for (int q = 0; q < 9; q++)
        out[q] = make_float4(acc[q*4], acc[q*4+1], acc[q*4+2], acc[q*4+3]);
}

// out[c*36 + b] = sum_{u,x} in[u*1296 + c*6 + x] * nodeL[(u*6+x)*36 + b]
__device__ __noinline__ void mpo_full36(int outOff, int inOff, int nodeOff, int tid)
{
    if (tid >= 216) return;
    float acc[36];
    #pragma unroll
    for (int i = 0; i < 36; i++) acc[i] = 0.0f;
    #pragma unroll 1
    for (int u = 0; u < 6; u++) {
        const float2* sp = (const float2*)(sm + inOff + u * 1296 + tid * 6);
        float2 s01 = sp[0], s23 = sp[1], s45 = sp[2];
        float sx[6] = {s01.x, s01.y, s23.x, s23.y, s45.x, s45.y};
        #pragma unroll
        for (int x = 0; x < 6; x++) {
            float sv = sx[x];
            const float4* nb = (const float4*)(sm + nodeOff + (u * 6 + x) * 36);
            #pragma unroll
            for (int q = 0; q < 9; q++) {
                float4 nv = nb[q];
                acc[q * 4 + 0] += sv * nv.x;
                acc[q * 4 + 1] += sv * nv.y;
                acc[q * 4 + 2] += sv * nv.z;
                acc[q * 4 + 3] += sv * nv.w;
            }
        }
    }
    float4* out = (float4*)(sm + outOff + tid * 36);
    #pragma unroll
    for (int q = 0; q < 9; q++)
        out[q] = make_float4(acc[q*4], acc[q*4+1], acc[q*4+2], acc[q*4+3]);
}

// out[c*6 + d] = sum_{u,x} in[u*1296 + c*6 + x] * nodeLa[(u*6+x)*6 + d]
__device__ __noinline__ void mpo_last36(int outOff, int inOff, int nodeOff, int tid)
{
    if (tid >= 216) return;
    float acc[6] = {0, 0, 0, 0, 0, 0};
    #pragma unroll 1
    for (int u = 0; u < 6; u++) {
        const float2* sp = (const float2*)(sm + inOff + u * 1296 + tid * 6);
        float2 s01 = sp[0], s23 = sp[1], s45 = sp[2];
        float sx[6] = {s01.x, s01.y, s23.x, s23.y, s45.x, s45.y};
        #pragma unroll
        for (int x = 0; x < 6; x++) {
            float sv = sx[x];
            const float2* nb = (const float2*)(sm + nodeOff + (u * 6 + x) * 6);
            float2 n01 = nb[0], n23 = nb[1], n45 = nb[2];
            acc[0] += sv * n01.x; acc[1] += sv * n01.y;
            acc[2] += sv * n23.x; acc[3] += sv * n23.y;
            acc[4] += sv * n45.x; acc[5] += sv * n45.y;
        }
    }
    float2* out = (float2*)(sm + outOff + tid * 6);
    out[0] = make_float2(acc[0], acc[1]);
    out[1] = make_float2(acc[2], acc[3]);
    out[2] = make_float2(acc[4], acc[5]);
}

// R[m*36 + d2*6 + l3] = sum_d3 EbT[d3*216 + d0d1*6 + d2] * n23[u3*36 + d3*6 + l3]
// with m = tid = u3*36 + d0d1
__device__ __noinline__ void rstep36(int outOff, int ebOff, int nodeOff, int tid)
{
    if (tid >= 216) return;
    int u3 = tid / 36;
    int dd = tid % 36;
    float acc[36];
    #pragma unroll
    for (int i = 0; i < 36; i++) acc[i] = 0.0f;
    #pragma unroll 1
    for (int d3 = 0; d3 < 6; d3++) {
        const float2* ep = (const float2*)(sm + ebOff + d3 * 216 + dd * 6);
        float2 e01 = ep[0], e23 = ep[1], e45 = ep[2];
        float eb[6] = {e01.x, e01.y, e23.x, e23.y, e45.x, e45.y};
        const float2* np = (const float2*)(sm + nodeOff + u3 * 36 + d3 * 6);
        float2 n01 = np[0], n23v = np[1], n45 = np[2];
        float nv[6] = {n01.x, n01.y, n23v.x, n23v.y, n45.x, n45.y};
        #pragma unroll
        for (int d2 = 0; d2 < 6; d2++)
            #pragma unroll
            for (int l3 = 0; l3 < 6; l3++)
                acc[d2 * 6 + l3] += eb[d2] * nv[l3];
    }
    float4* out = (float4*)(sm + outOff + tid * 36);
    #pragma unroll
    for (int q = 0; q < 9; q++)
        out[q] = make_float4(acc[q*4], acc[q*4+1], acc[q*4+2], acc[q*4+3]);
}

// T[u*216 + r*36 + d*6 + l] = sum_m L[u*1296 + m*6 + l] * R[m*36 + d*6 + r]
// 2(l) x 4(beta=d*6+r) register tile, 162 threads
__device__ __noinline__ void tgemm_tiled(int tOff, int lOff, int rOff, int tid)
{
    if (tid >= 162) return;
    int pr = tid / 9;           // 0..17  -> (u, l-pair)
    int bt = tid % 9;           // 0..8   -> beta tile of 4
    int u  = pr / 3;
    int l0 = (pr % 3) * 2;
    int b0 = bt * 4;
    float acc[8];
    #pragma unroll
    for (int i = 0; i < 8; i++) acc[i] = 0.0f;
    const float* Lp = sm + lOff + u * 1296 + l0;
    const float* Rp = sm + rOff + b0;
    #pragma unroll 4
    for (int m = 0; m < 216; m++) {
        float2 a  = *(const float2*)(Lp + m * 6);
        float4 bv = *(const float4*)(Rp + m * 36);
        acc[0] += a.x * bv.x; acc[1] += a.x * bv.y;
        acc[2] += a.x * bv.z; acc[3] += a.x * bv.w;
        acc[4] += a.y * bv.x; acc[5] += a.y * bv.y;
        acc[6] += a.y * bv.z; acc[7] += a.y * bv.w;
    }
    #pragma unroll
    for (int j = 0; j < 4; j++) {
        int beta = b0 + j;
        int d = beta / 6;
        int r = beta % 6;
        sm[tOff + u * 216 + r * 36 + d * 6 + l0]     = acc[j];
        sm[tOff + u * 216 + r * 36 + d * 6 + l0 + 1] = acc[4 + j];
    }
}

// ---------------------------------------------------------------------------
// kernel: one block per batch element
// ---------------------------------------------------------------------------

__global__ __launch_bounds__(NT, 3)
void peps_forward_kernel(const float* __restrict__ inputs,
                         const float* __restrict__ peps,
                         const float* __restrict__ pepsc,
                         float* __restrict__ out, int B)
{
    const int tid = threadIdx.x;
    const int b = blockIdx.x;

    if (tid < 32) sm[OFF_X + tid] = inputs[b * 32 + tid];
    __syncthreads();

    #define PB(i, j)  (peps + ((i) * 4 + (j)) * 2 * 1296)
    #define XX0(i, j) sm[OFF_X + ((i) * 4 + (j)) * 2]
    #define XX1(i, j) sm[OFF_X + ((i) * 4 + (j)) * 2 + 1]

    const int P0 = OFF_A;            // 1296 ping
    const int P1 = OFF_A + 1296;     // 1296 pong

    // ================= Row 0 (top boundary, u=0) =================
    load_node(OFF_N, PB(0, 0), XX0(0, 0), XX1(0, 0), 6, 6, 1, 36, 6, 0, tid);
    __syncthreads();
    for (int k = tid; k < 36; k += NT) { int d0 = k / 6, r = k % 6; sm[P0 + k] = sm[OFF_N + r * 6 + d0]; }
    __syncthreads();
    load_node(OFF_N, PB(0, 1), XX0(0, 1), XX1(0, 1), 6, 6, 6, 36, 6, 1, tid);
    __syncthreads();
    rowstep(P1, P0, OFF_N, 6, false, tid);
    __syncthreads();
    load_node(OFF_N, PB(0, 2), XX0(0, 2), XX1(0, 2), 6, 6, 6, 36, 6, 1, tid);
    __syncthreads();
    rowstep(P0, P1, OFF_N, 36, false, tid);
    __syncthreads();
    load_node(OFF_N, PB(0, 3), XX0(0, 3), XX1(0, 3), 6, 6, 1, 6, 1, 0, tid);
    __syncthreads();
    laststep(P1, P0, OFF_N, tid);
    __syncthreads();
    unit_norm(OFF_E, P1, 1296, tid);               // env0 -> sE

    // ================= Row 1 (MPO) =================
    load_node(OFF_N, PB(1, 0), XX0(1, 0), XX1(1, 0), 6, 6, 6, 216, 6, 36, tid);   // [u][d][r]
    __syncthreads();
    mpo_first36(OFF_A, OFF_E, OFF_N, tid);
    __syncthreads();
    load_node_full(OFF_N, PB(1, 1), XX0(1, 1), XX1(1, 1), tid);
    __syncthreads();
    mpo_full36(OFF_B, OFF_A, OFF_N, tid);
    __syncthreads();
    load_node_full(OFF_N, PB(1, 2), XX0(1, 2), XX1(1, 2), tid);
    __syncthreads();
    mpo_full36(OFF_A, OFF_B, OFF_N, tid);
    __syncthreads();
    load_node(OFF_N, PB(1, 3), XX0(1, 3), XX1(1, 3), 6, 6, 6, 216, 1, 6, tid);    // [u][x][d]
    __syncthreads();
    mpo_last36(OFF_B, OFF_A, OFF_N, tid);
    __syncthreads();
    unit_norm(OFF_E, OFF_B, 1296, tid);            // env_top -> sE

    // ================= Row 2 L-part (consumes env_top now) =================
    load_node(OFF_N, PB(2, 0), XX0(2, 0), XX1(2, 0), 6, 6, 6, 216, 6, 36, tid);   // [u][d][r]
    __syncthreads();
    mpo_first36(OFF_A, OFF_E, OFF_N, tid);         // L1 -> sA  (env_top dead)
    __syncthreads();
    load_node_full(OFF_N, PB(2, 1), XX0(2, 1), XX1(2, 1), tid);
    __syncthreads();
    mpo_full36(OFF_B, OFF_A, OFF_N, tid);          // L2 -> sB (persists)
    __syncthreads();

    // ================= Row 3 (bottom boundary, d=0; scratch inside sA) ======
    load_node(OFF_N, PB(3, 0), XX0(3, 0), XX1(3, 0), 6, 6, 1, 216, 36, 0, tid);
    __syncthreads();
    for (int k = tid; k < 36; k += NT) sm[P0 + k] = sm[OFF_N + k];
    __syncthreads();
    load_node(OFF_N, PB(3, 1), XX0(3, 1), XX1(3, 1), 6, 6, 6, 216, 36, 1, tid);
    __syncthreads();
    rowstep(P1, P0, OFF_N, 6, true, tid);
    __syncthreads();
    load_node(OFF_N, PB(3, 2), XX0(3, 2), XX1(3, 2), 6, 6, 6, 216, 36, 1, tid);
    __syncthreads();
    rowstep(P0, P1, OFF_N, 36, true, tid);
    __syncthreads();
    load_node(OFF_N, PB(3, 3), XX0(3, 3), XX1(3, 3), 6, 6, 1, 216, 1, 0, tid);
    __syncthreads();
    laststep(P1, P0, OFF_N, tid);
    __syncthreads();
    unit_norm_T(OFF_E, P1, tid);                   // env_bot (transposed) -> sE

    // ================= Row 2 R-part + merge =================
    load_node(OFF_N, PB(2, 3), XX0(2, 3), XX1(2, 3), 6, 6, 6, 216, 6, 1, tid);    // [u][d][l]
    __syncthreads();
    rstep36(OFF_A, OFF_E, OFF_N, tid);             // R -> sA (env_botT dead)
    __syncthreads();
    tgemm_tiled(OFF_E, OFF_B, OFF_A, tid);         // T -> sE
    __syncthreads();

    // ================= Final contraction with peps_center =================
    const float xc0 = XX0(2, 2);
    const float xc1 = XX1(2, 2);
    for (int o = 0; o < 10; o++) {
        float v = 0.0f;
        const float* p0 = pepsc + o * 1296;
        const float* p1 = pepsc + 12960 + o * 1296;
        for (int k = tid; k < 1296; k += NT)
            v += sm[OFF_E + k] * (xc0 * p0[k] + xc1 * p1[k]);
        float s = block_reduce_sum(v, tid);
        if (tid == 0) sm[OFF_OUT + o] = s;
        __syncthreads();
    }

    if (tid < 10) {
        float nrm = 0.0f;
        #pragma unroll
        for (int o = 0; o < 10; o++) { float t = sm[OFF_OUT + o]; nrm += t * t; }
        out[b * 10 + tid] = sm[OFF_OUT + tid] * rsqrtf(nrm);
    }
}

// ---------------------------------------------------------------------------
// launch
// ---------------------------------------------------------------------------

extern "C" void kernel_launch(void* const* d_in, const int* in_sizes, int n_in,
                              void* d_out, int out_size)
{
    const float* inputs = (const float*)d_in[0];   // (B,4,4,2)
    const float* peps   = (const float*)d_in[1];   // (4,4,2,6,6,6,6)
    const float* pepsc  = (const float*)d_in[2];   // (2,10,6,6,6,6)
    float* out = (float*)d_out;                    // (B,10)

    const int B = in_sizes[0] / 32;

    cudaFuncSetAttribute(peps_forward_kernel,
                         cudaFuncAttributeMaxDynamicSharedMemorySize, SMEM_BYTES);
    peps_forward_kernel<<<B, NT, SMEM_BYTES>>>(inputs, peps, pepsc, out, B);
}

// round 3
// speedup vs baseline: 1.8081x; 1.1831x over previous
#include <cuda_runtime.h>

#define NT 224

// shared-memory layout (float offsets)
#define OFF_A    0        // 7776  scratch A / L1 / R / row0+row3 ping-pong / warp partials
#define OFF_B    7776     // 7776  scratch B / L2
#define OFF_N    15552    // 1296  node buffer
#define OFF_E    16848    // 1296  env0 / env_top / env_botT / T
#define OFF_RED  18144    // 32
#define OFF_OUT  18176    // 16
#define OFF_X    18192    // 32
#define SMEM_FLOATS 18224
#define SMEM_BYTES  (SMEM_FLOATS * 4)

extern __shared__ float sm[];

// ---------------------------------------------------------------------------
// reductions
// ---------------------------------------------------------------------------

__device__ __forceinline__ float block_reduce_sum(float v, int tid)
{
    float* sRed = sm + OFF_RED;
    #pragma unroll
    for (int o = 16; o > 0; o >>= 1) v += __shfl_down_sync(0xffffffffu, v, o);
    if ((tid & 31) == 0) sRed[tid >> 5] = v;
    __syncthreads();
    if (tid < 32) {
        float w = (tid < (NT >> 5)) ? sRed[tid] : 0.0f;
        #pragma unroll
        for (int o = 4; o > 0; o >>= 1) w += __shfl_down_sync(0xffffffffu, w, o);
        if (tid == 0) sRed[0] = w;
    }
    __syncthreads();
    float r = sRed[0];
    __syncthreads();
    return r;
}

__device__ __forceinline__ void unit_norm(int dstOff, int srcOff, int n, int tid)
{
    float v = 0.0f;
    for (int k = tid; k < n; k += NT) { float t = sm[srcOff + k]; v += t * t; }
    float sc = rsqrtf(block_reduce_sum(v, tid));
    for (int k = tid; k < n; k += NT) sm[dstOff + k] = sm[srcOff + k] * sc;
    __syncthreads();
}

// env_bot, transposed:  dst[d3*216 + d0d1*6 + d2] = src[d0d1*36 + d2*6 + d3] * sc
__device__ __forceinline__ void unit_norm_T(int dstOff, int srcOff, int tid)
{
    float v = 0.0f;
    for (int k = tid; k < 1296; k += NT) { float t = sm[srcOff + k]; v += t * t; }
    float sc = rsqrtf(block_reduce_sum(v, tid));
    for (int k = tid; k < 1296; k += NT) {
        int dd = k / 36;
        int d2 = (k / 6) % 6;
        int d3 = k % 6;
        sm[dstOff + d3 * 216 + dd * 6 + d2] = sm[srcOff + k] * sc;
    }
    __syncthreads();
}

// ---------------------------------------------------------------------------
// node loaders (node = x0 * P[slice] + x1 * P[1296 + slice])
// ---------------------------------------------------------------------------

__device__ __forceinline__ void load_node(int nodeOff, const float* __restrict__ P,
                                          float x0, float x1,
                                          int ca, int cb, int cc,
                                          int sa, int sb, int sc, int tid)
{
    const int n = ca * cb * cc;
    for (int k = tid; k < n; k += NT) {
        int a   = k / (cb * cc);
        int rem = k - a * (cb * cc);
        int bb  = rem / cc;
        int c   = rem - bb * cc;
        int addr = a * sa + bb * sb + c * sc;
        sm[nodeOff + k] = x0 * P[addr] + x1 * P[addr + 1296];
    }
}

// full node for mpo_full: nodeL[((u*6+x)*6+d)*6 + r] = n[u][r][d][x]
__device__ __forceinline__ void load_node_full(int nodeOff, const float* __restrict__ P,
                                               float x0, float x1, int tid)
{
    for (int k = tid; k < 1296; k += NT) {
        int u   = k / 216;
        int rem = k % 216;
        int x   = rem / 36;  rem %= 36;
        int d   = rem / 6;
        int r   = rem % 6;
        int addr = u * 216 + r * 36 + d * 6 + x;
        sm[nodeOff + k] = x0 * P[addr] + x1 * P[addr + 1296];
    }
}

// ---------------------------------------------------------------------------
// small-row helpers (rows 0 and 3)
// ---------------------------------------------------------------------------

__device__ __forceinline__ void rowstep(int outOff, int inOff, int nodeOff,
                                        int As, bool swap, int tid)
{
    const int n = As * 36;
    for (int k = tid; k < n; k += NT) {
        int A = k / 36;
        int p = (k / 6) % 6;
        int q = k % 6;
        int nb = (swap ? (p * 6 + q) : (q * 6 + p)) * 6;
        const float2* ip = (const float2*)(sm + inOff + A * 6);
        float2 i01 = ip[0], i23 = ip[1], i45 = ip[2];
        float acc = i01.x * sm[nodeOff + nb + 0] + i01.y * sm[nodeOff + nb + 1]
                  + i23.x * sm[nodeOff + nb + 2] + i23.y * sm[nodeOff + nb + 3]
                  + i45.x * sm[nodeOff + nb + 4] + i45.y * sm[nodeOff + nb + 5];
        sm[outOff + k] = acc;
    }
}

__device__ __forceinline__ void laststep(int outOff, int inOff, int nodeOff, int tid)
{
    for (int k = tid; k < 1296; k += NT) {
        int A = k / 6;
        int p = k % 6;
        const float2* ip = (const float2*)(sm + inOff + A * 6);
        float2 i01 = ip[0], i23 = ip[1], i45 = ip[2];
        const float* nb = sm + nodeOff + p * 6;
        float acc = i01.x * nb[0] + i01.y * nb[1]
                  + i23.x * nb[2] + i23.y * nb[3]
                  + i45.x * nb[4] + i45.y * nb[5];
        sm[outOff + k] = acc;
    }
}

// ---------------------------------------------------------------------------
// MPO kernels: 3(row) x 12(col) register tiles, 216 threads
// thread tid -> rg = tid/3 (rows c = rg*3+rr), cg = tid%3 (cols b = cg*12+j)
// ---------------------------------------------------------------------------

// out[c*36 + b] = sum_u E[u*216 + c] * nodeF[u*36 + b]
__device__ __noinline__ void mpo_first36(int outOff, int eOff, int nodeOff, int tid)
{
    if (tid >= 216) return;
    const int rg = tid / 3;
    const int cg = tid % 3;
    float acc[3][12];
    #pragma unroll
    for (int rr = 0; rr < 3; rr++)
        #pragma unroll
        for (int j = 0; j < 12; j++) acc[rr][j] = 0.0f;
    #pragma unroll 1
    for (int u = 0; u < 6; u++) {
        float e[3];
        #pragma unroll
        for (int rr = 0; rr < 3; rr++) e[rr] = sm[eOff + u * 216 + rg * 3 + rr];
        const float4* nb = (const float4*)(sm + nodeOff + u * 36 + cg * 12);
        float4 n0 = nb[0], n1 = nb[1], n2 = nb[2];
        #pragma unroll
        for (int rr = 0; rr < 3; rr++) {
            acc[rr][0] += e[rr] * n0.x; acc[rr][1]  += e[rr] * n0.y;
            acc[rr][2] += e[rr] * n0.z; acc[rr][3]  += e[rr] * n0.w;
            acc[rr][4] += e[rr] * n1.x; acc[rr][5]  += e[rr] * n1.y;
            acc[rr][6] += e[rr] * n1.z; acc[rr][7]  += e[rr] * n1.w;
            acc[rr][8] += e[rr] * n2.x; acc[rr][9]  += e[rr] * n2.y;
            acc[rr][10]+= e[rr] * n2.z; acc[rr][11] += e[rr] * n2.w;
        }
    }
    #pragma unroll
    for (int rr = 0; rr < 3; rr++) {
        float4* out = (float4*)(sm + outOff + (rg * 3 + rr) * 36 + cg * 12);
        out[0] = make_float4(acc[rr][0], acc[rr][1], acc[rr][2], acc[rr][3]);
        out[1] = make_float4(acc[rr][4], acc[rr][5], acc[rr][6], acc[rr][7]);
        out[2] = make_float4(acc[rr][8], acc[rr][9], acc[rr][10], acc[rr][11]);
    }
}

// out[c*36 + b] = sum_{u,x} in[u*1296 + c*6 + x] * nodeL[(u*6+x)*36 + b]
__device__ __noinline__ void mpo_full36(int outOff, int inOff, int nodeOff, int tid)
{
    if (tid >= 216) return;
    const int rg = tid / 3;
    const int cg = tid % 3;
    float acc[3][12];
    #pragma unroll
    for (int rr = 0; rr < 3; rr++)
        #pragma unroll
        for (int j = 0; j < 12; j++) acc[rr][j] = 0.0f;
    #pragma unroll 1
    for (int u = 0; u < 6; u++) {
        float a[3][6];
        #pragma unroll
        for (int rr = 0; rr < 3; rr++) {
            const float2* sp = (const float2*)(sm + inOff + u * 1296 + (rg * 3 + rr) * 6);
            float2 s01 = sp[0], s23 = sp[1], s45 = sp[2];
            a[rr][0] = s01.x; a[rr][1] = s01.y;
            a[rr][2] = s23.x; a[rr][3] = s23.y;
            a[rr][4] = s45.x; a[rr][5] = s45.y;
        }
        #pragma unroll
        for (int x = 0; x < 6; x++) {
            const float4* nb = (const float4*)(sm + nodeOff + (u * 6 + x) * 36 + cg * 12);
            float4 n0 = nb[0], n1 = nb[1], n2 = nb[2];
            #pragma unroll
            for (int rr = 0; rr < 3; rr++) {
                float sv = a[rr][x];
                acc[rr][0] += sv * n0.x; acc[rr][1]  += sv * n0.y;
                acc[rr][2] += sv * n0.z; acc[rr][3]  += sv * n0.w;
                acc[rr][4] += sv * n1.x; acc[rr][5]  += sv * n1.y;
                acc[rr][6] += sv * n1.z; acc[rr][7]  += sv * n1.w;
                acc[rr][8] += sv * n2.x; acc[rr][9]  += sv * n2.y;
                acc[rr][10]+= sv * n2.z; acc[rr][11] += sv * n2.w;
            }
        }
    }
    #pragma unroll
    for (int rr = 0; rr < 3; rr++) {
        float4* out = (float4*)(sm + outOff + (rg * 3 + rr) * 36 + cg * 12);
        out[0] = make_float4(acc[rr][0], acc[rr][1], acc[rr][2], acc[rr][3]);
        out[1] = make_float4(acc[rr][4], acc[rr][5], acc[rr][6], acc[rr][7]);
        out[2] = make_float4(acc[rr][8], acc[rr][9], acc[rr][10], acc[rr][11]);
    }
}

// out[c*6 + d] = sum_{u,x} in[u*1296 + c*6 + x] * nodeLa[(u*6+x)*6 + d]
__device__ __noinline__ void mpo_last36(int outOff, int inOff, int nodeOff, int tid)
{
    if (tid >= 216) return;
    float acc[6] = {0, 0, 0, 0, 0, 0};
    #pragma unroll 1
    for (int u = 0; u < 6; u++) {
        const float2* sp = (const float2*)(sm + inOff + u * 1296 + tid * 6);
        float2 s01 = sp[0], s23 = sp[1], s45 = sp[2];
        float sx[6] = {s01.x, s01.y, s23.x, s23.y, s45.x, s45.y};
        #pragma unroll
        for (int x = 0; x < 6; x++) {
            float sv = sx[x];
            const float2* nb = (const float2*)(sm + nodeOff + (u * 6 + x) * 6);
            float2 n01 = nb[0], n23 = nb[1], n45 = nb[2];
            acc[0] += sv * n01.x; acc[1] += sv * n01.y;
            acc[2] += sv * n23.x; acc[3] += sv * n23.y;
            acc[4] += sv * n45.x; acc[5] += sv * n45.y;
        }
    }
    float2* out = (float2*)(sm + outOff + tid * 6);
    out[0] = make_float2(acc[0], acc[1]);
    out[1] = make_float2(acc[2], acc[3]);
    out[2] = make_float2(acc[4], acc[5]);
}

// R[m*36 + d2*6 + l3] = sum_d3 EbT[d3*216 + d0d1*6 + d2] * n23[u3*36 + d3*6 + l3]
__device__ __noinline__ void rstep36(int outOff, int ebOff, int nodeOff, int tid)
{
    if (tid >= 216) return;
    int u3 = tid / 36;
    int dd = tid % 36;
    float acc[36];
    #pragma unroll
    for (int i = 0; i < 36; i++) acc[i] = 0.0f;
    #pragma unroll 1
    for (int d3 = 0; d3 < 6; d3++) {
        const float2* ep = (const float2*)(sm + ebOff + d3 * 216 + dd * 6);
        float2 e01 = ep[0], e23 = ep[1], e45 = ep[2];
        float eb[6] = {e01.x, e01.y, e23.x, e23.y, e45.x, e45.y};
        const float2* np = (const float2*)(sm + nodeOff + u3 * 36 + d3 * 6);
        float2 n01 = np[0], n23v = np[1], n45 = np[2];
        float nv[6] = {n01.x, n01.y, n23v.x, n23v.y, n45.x, n45.y};
        #pragma unroll
        for (int d2 = 0; d2 < 6; d2++)
            #pragma unroll
            for (int l3 = 0; l3 < 6; l3++)
                acc[d2 * 6 + l3] += eb[d2] * nv[l3];
    }
    float4* out = (float4*)(sm + outOff + tid * 36);
    #pragma unroll
    for (int q = 0; q < 9; q++)
        out[q] = make_float4(acc[q*4], acc[q*4+1], acc[q*4+2], acc[q*4+3]);
}

// T[u*216 + r*36 + d*6 + l] = sum_m L[u*1296 + m*6 + l] * R[m*36 + d*6 + r]
__device__ __noinline__ void tgemm_tiled(int tOff, int lOff, int rOff, int tid)
{
    if (tid >= 162) return;
    int pr = tid / 9;
    int bt = tid % 9;
    int u  = pr / 3;
    int l0 = (pr % 3) * 2;
    int b0 = bt * 4;
    float acc[8];
    #pragma unroll
    for (int i = 0; i < 8; i++) acc[i] = 0.0f;
    const float* Lp = sm + lOff + u * 1296 + l0;
    const float* Rp = sm + rOff + b0;
    #pragma unroll 4
    for (int m = 0; m < 216; m++) {
        float2 a  = *(const float2*)(Lp + m * 6);
        float4 bv = *(const float4*)(Rp + m * 36);
        acc[0] += a.x * bv.x; acc[1] += a.x * bv.y;
        acc[2] += a.x * bv.z; acc[3] += a.x * bv.w;
        acc[4] += a.y * bv.x; acc[5] += a.y * bv.y;
        acc[6] += a.y * bv.z; acc[7] += a.y * bv.w;
    }
    #pragma unroll
    for (int j = 0; j < 4; j++) {
        int beta = b0 + j;
        int d = beta / 6;
        int r = beta % 6;
        sm[tOff + u * 216 + r * 36 + d * 6 + l0]     = acc[j];
        sm[tOff + u * 216 + r * 36 + d * 6 + l0 + 1] = acc[4 + j];
    }
}

// ---------------------------------------------------------------------------
// kernel: one block per batch element
// ---------------------------------------------------------------------------

__global__ __launch_bounds__(NT, 3)
void peps_forward_kernel(const float* __restrict__ inputs,
                         const float* __restrict__ peps,
                         const float* __restrict__ pepsc,
                         float* __restrict__ out, int B)
{
    const int tid = threadIdx.x;
    const int b = blockIdx.x;

    if (tid < 32) sm[OFF_X + tid] = inputs[b * 32 + tid];
    __syncthreads();

    #define PB(i, j)  (peps + ((i) * 4 + (j)) * 2 * 1296)
    #define XX0(i, j) sm[OFF_X + ((i) * 4 + (j)) * 2]
    #define XX1(i, j) sm[OFF_X + ((i) * 4 + (j)) * 2 + 1]

    const int P0 = OFF_A;
    const int P1 = OFF_A + 1296;

    // ================= Row 0 (top boundary, u=0) =================
    load_node(OFF_N, PB(0, 0), XX0(0, 0), XX1(0, 0), 6, 6, 1, 36, 6, 0, tid);
    __syncthreads();
    for (int k = tid; k < 36; k += NT) { int d0 = k / 6, r = k % 6; sm[P0 + k] = sm[OFF_N + r * 6 + d0]; }
    __syncthreads();
    load_node(OFF_N, PB(0, 1), XX0(0, 1), XX1(0, 1), 6, 6, 6, 36, 6, 1, tid);
    __syncthreads();
    rowstep(P1, P0, OFF_N, 6, false, tid);
    __syncthreads();
    load_node(OFF_N, PB(0, 2), XX0(0, 2), XX1(0, 2), 6, 6, 6, 36, 6, 1, tid);
    __syncthreads();
    rowstep(P0, P1, OFF_N, 36, false, tid);
    __syncthreads();
    load_node(OFF_N, PB(0, 3), XX0(0, 3), XX1(0, 3), 6, 6, 1, 6, 1, 0, tid);
    __syncthreads();
    laststep(P1, P0, OFF_N, tid);
    __syncthreads();
    unit_norm(OFF_E, P1, 1296, tid);               // env0 -> sE

    // ================= Row 1 (MPO) =================
    load_node(OFF_N, PB(1, 0), XX0(1, 0), XX1(1, 0), 6, 6, 6, 216, 6, 36, tid);   // [u][d][r]
    __syncthreads();
    mpo_first36(OFF_A, OFF_E, OFF_N, tid);
    __syncthreads();
    load_node_full(OFF_N, PB(1, 1), XX0(1, 1), XX1(1, 1), tid);
    __syncthreads();
    mpo_full36(OFF_B, OFF_A, OFF_N, tid);
    __syncthreads();
    load_node_full(OFF_N, PB(1, 2), XX0(1, 2), XX1(1, 2), tid);
    __syncthreads();
    mpo_full36(OFF_A, OFF_B, OFF_N, tid);
    __syncthreads();
    load_node(OFF_N, PB(1, 3), XX0(1, 3), XX1(1, 3), 6, 6, 6, 216, 1, 6, tid);    // [u][x][d]
    __syncthreads();
    mpo_last36(OFF_B, OFF_A, OFF_N, tid);
    __syncthreads();
    unit_norm(OFF_E, OFF_B, 1296, tid);            // env_top -> sE

    // ================= Row 2 L-part =================
    load_node(OFF_N, PB(2, 0), XX0(2, 0), XX1(2, 0), 6, 6, 6, 216, 6, 36, tid);   // [u][d][r]
    __syncthreads();
    mpo_first36(OFF_A, OFF_E, OFF_N, tid);         // L1 -> sA
    __syncthreads();
    load_node_full(OFF_N, PB(2, 1), XX0(2, 1), XX1(2, 1), tid);
    __syncthreads();
    mpo_full36(OFF_B, OFF_A, OFF_N, tid);          // L2 -> sB (persists)
    __syncthreads();

    // ================= Row 3 (bottom boundary, d=0) =================
    load_node(OFF_N, PB(3, 0), XX0(3, 0), XX1(3, 0), 6, 6, 1, 216, 36, 0, tid);
    __syncthreads();
    for (int k = tid; k < 36; k += NT) sm[P0 + k] = sm[OFF_N + k];
    __syncthreads();
    load_node(OFF_N, PB(3, 1), XX0(3, 1), XX1(3, 1), 6, 6, 6, 216, 36, 1, tid);
    __syncthreads();
    rowstep(P1, P0, OFF_N, 6, true, tid);
    __syncthreads();
    load_node(OFF_N, PB(3, 2), XX0(3, 2), XX1(3, 2), 6, 6, 6, 216, 36, 1, tid);
    __syncthreads();
    rowstep(P0, P1, OFF_N, 36, true, tid);
    __syncthreads();
    load_node(OFF_N, PB(3, 3), XX0(3, 3), XX1(3, 3), 6, 6, 1, 216, 1, 0, tid);
    __syncthreads();
    laststep(P1, P0, OFF_N, tid);
    __syncthreads();
    unit_norm_T(OFF_E, P1, tid);                   // env_bot (transposed) -> sE

    // ================= Row 2 R-part + merge =================
    load_node(OFF_N, PB(2, 3), XX0(2, 3), XX1(2, 3), 6, 6, 6, 216, 6, 1, tid);    // [u][d][l]
    __syncthreads();
    rstep36(OFF_A, OFF_E, OFF_N, tid);             // R -> sA
    __syncthreads();
    if (tid < 16) sm[OFF_OUT + tid] = 0.0f;
    tgemm_tiled(OFF_E, OFF_B, OFF_A, tid);         // T -> sE
    __syncthreads();

    // ================= Final contraction with peps_center (single pass) ====
    {
        const float xc0 = XX0(2, 2);
        const float xc1 = XX1(2, 2);
        float acc[10];
        #pragma unroll
        for (int o = 0; o < 10; o++) acc[o] = 0.0f;
        for (int k = tid; k < 1296; k += NT) {
            float e  = sm[OFF_E + k];
            float e0 = e * xc0;
            float e1 = e * xc1;
            #pragma unroll
            for (int o = 0; o < 10; o++)
                acc[o] += e0 * pepsc[o * 1296 + k] + e1 * pepsc[12960 + o * 1296 + k];
        }
        // warp-level reduce, then deterministic tree over the 7 warp partials
        #pragma unroll
        for (int o = 0; o < 10; o++)
            #pragma unroll
            for (int off = 16; off > 0; off >>= 1)
                acc[o] += __shfl_down_sync(0xffffffffu, acc[o], off);
        const int w = tid >> 5;
        if ((tid & 31) == 0) {
            #pragma unroll
            for (int o = 0; o < 10; o++) sm[OFF_A + w * 10 + o] = acc[o];
        }
        __syncthreads();
        if (tid < 10) {
            float s = 0.0f;
            #pragma unroll
            for (int ww = 0; ww < (NT >> 5); ww++) s += sm[OFF_A + ww * 10 + tid];
            sm[OFF_OUT + tid] = s;
        }
        __syncthreads();
    }

    if (tid < 10) {
        float nrm = 0.0f;
        #pragma unroll
        for (int o = 0; o < 10; o++) { float t = sm[OFF_OUT + o]; nrm += t * t; }
        out[b * 10 + tid] = sm[OFF_OUT + tid] * rsqrtf(nrm);
    }
}

// ---------------------------------------------------------------------------
// launch
// ---------------------------------------------------------------------------

extern "C" void kernel_launch(void* const* d_in, const int* in_sizes, int n_in,
                              void* d_out, int out_size)
{
    const float* inputs = (const float*)d_in[0];   // (B,4,4,2)
    const float* peps   = (const float*)d_in[1];   // (4,4,2,6,6,6,6)
    const float* pepsc  = (const float*)d_in[2];   // (2,10,6,6,6,6)
    float* out = (float*)d_out;                    // (B,10)

    const int B = in_sizes[0] / 32;

    cudaFuncSetAttribute(peps_forward_kernel,
                         cudaFuncAttributeMaxDynamicSharedMemorySize, SMEM_BYTES);
    peps_forward_kernel<<<B, NT, SMEM_BYTES>>>(inputs, peps, pepsc, out, B);
}

// round 4
// speedup vs baseline: 1.9262x; 1.0653x over previous
#include <cuda_runtime.h>

#define NT 224

// shared-memory layout (float offsets)
#define OFF_A    0        // 7776  MPO ping / row ping-pong / R / warp partials
#define OFF_B    7776     // 7776  MPO pong / env0 / env_top / L2
#define OFF_N    15552    // 2592  node double-buffer: H0, H1
#define OFF_RED  18144    // 8
#define OFF_OUT  18152    // 12
#define OFF_X    18164    // 32
#define SMEM_FLOATS 18208
#define SMEM_BYTES  (SMEM_FLOATS * 4)

#define H0 (OFF_N)
#define H1 (OFF_N + 1296)

extern __shared__ float sm[];

// ---------------------------------------------------------------------------
// sumsq all-reduce: every warp publishes its partial; all threads re-sum
// ---------------------------------------------------------------------------

__device__ __forceinline__ void sumsq_publish(float v, int tid)
{
    #pragma unroll
    for (int o = 16; o > 0; o >>= 1) v += __shfl_down_sync(0xffffffffu, v, o);
    if ((tid & 31) == 0) sm[OFF_RED + (tid >> 5)] = v;
}

__device__ __forceinline__ float read_scale()
{
    float s = 0.0f;
    #pragma unroll
    for (int w = 0; w < 7; w++) s += sm[OFF_RED + w];
    return rsqrtf(s);
}

// ---------------------------------------------------------------------------
// node prefetch (global -> regs) and commit (regs -> smem)
// node = x0 * P[slice] + x1 * P[1296 + slice]
// ---------------------------------------------------------------------------

__device__ __forceinline__ float pf_slice(const float* __restrict__ P,
                                          float x0, float x1,
                                          int cb, int cc,
                                          int sa, int sb, int sc,
                                          int n, int tid)
{
    if (tid >= n) return 0.0f;
    int a   = tid / (cb * cc);
    int rem = tid - a * (cb * cc);
    int bb  = rem / cc;
    int c   = rem - bb * cc;
    int addr = a * sa + bb * sb + c * sc;
    return x0 * __ldg(P + addr) + x1 * __ldg(P + addr + 1296);
}

__device__ __forceinline__ void st_slice(int off, float v, int n, int tid, float scale)
{
    if (tid < n) sm[off + tid] = v * scale;
}

// full node for mpo_full: buffer[(u*6+x)*36 + d*6 + r] from tensor [u][r][d][x]
__device__ __forceinline__ void pf_full(float* v, const float* __restrict__ P,
                                        float x0, float x1, int tid)
{
    #pragma unroll
    for (int i = 0; i < 6; i++) {
        int k = tid + i * NT;
        if (k < 1296) {
            int u = k / 216, rem = k % 216;
            int x = rem / 36; rem %= 36;
            int d = rem / 6, r = rem % 6;
            int addr = u * 216 + r * 36 + d * 6 + x;
            v[i] = x0 * __ldg(P + addr) + x1 * __ldg(P + addr + 1296);
        }
    }
}

__device__ __forceinline__ void st_full(int off, const float* v, int tid)
{
    #pragma unroll
    for (int i = 0; i < 6; i++) {
        int k = tid + i * NT;
        if (k < 1296) sm[off + k] = v[i];
    }
}

// ---------------------------------------------------------------------------
// small-row helpers (rows 0 and 3)
// ---------------------------------------------------------------------------

__device__ __forceinline__ void rowstep(int outOff, int inOff, int nodeOff,
                                        int As, bool swap, int tid)
{
    const int n = As * 36;
    for (int k = tid; k < n; k += NT) {
        int A = k / 36;
        int p = (k / 6) % 6;
        int q = k % 6;
        int nb = (swap ? (p * 6 + q) : (q * 6 + p)) * 6;
        const float2* ip = (const float2*)(sm + inOff + A * 6);
        float2 i01 = ip[0], i23 = ip[1], i45 = ip[2];
        float acc = i01.x * sm[nodeOff + nb + 0] + i01.y * sm[nodeOff + nb + 1]
                  + i23.x * sm[nodeOff + nb + 2] + i23.y * sm[nodeOff + nb + 3]
                  + i45.x * sm[nodeOff + nb + 4] + i45.y * sm[nodeOff + nb + 5];
        sm[outOff + k] = acc;
    }
}

// row0 final step: writes env raw, returns sumsq partial
__device__ __forceinline__ float laststep_sq(int outOff, int inOff, int nodeOff, int tid)
{
    float ss = 0.0f;
    for (int k = tid; k < 1296; k += NT) {
        int A = k / 6;
        int p = k % 6;
        const float2* ip = (const float2*)(sm + inOff + A * 6);
        float2 i01 = ip[0], i23 = ip[1], i45 = ip[2];
        const float* nb = sm + nodeOff + p * 6;
        float acc = i01.x * nb[0] + i01.y * nb[1]
                  + i23.x * nb[2] + i23.y * nb[3]
                  + i45.x * nb[4] + i45.y * nb[5];
        ss += acc * acc;
        sm[outOff + k] = acc;
    }
    return ss;
}

// row3 final step: writes env TRANSPOSED ([d3][d0d1][d2]) raw, returns sumsq
__device__ __forceinline__ float laststep_T_sq(int outOff, int inOff, int nodeOff, int tid)
{
    float ss = 0.0f;
    for (int k = tid; k < 1296; k += NT) {
        int A = k / 6;
        int p = k % 6;
        const float2* ip = (const float2*)(sm + inOff + A * 6);
        float2 i01 = ip[0], i23 = ip[1], i45 = ip[2];
        const float* nb = sm + nodeOff + p * 6;
        float acc = i01.x * nb[0] + i01.y * nb[1]
                  + i23.x * nb[2] + i23.y * nb[3]
                  + i45.x * nb[4] + i45.y * nb[5];
        ss += acc * acc;
        sm[outOff + p * 216 + (A / 6) * 6 + (A % 6)] = acc;
    }
    return ss;
}

// ---------------------------------------------------------------------------
// MPO kernels: 3(row) x 12(col) register tiles, 216 threads
// ---------------------------------------------------------------------------

// out[c*36 + b] = sum_u E[u*216 + c] * nodeF[u*36 + b]
__device__ __forceinline__ void mpo_first36(int outOff, int eOff, int nodeOff, int tid)
{
    if (tid >= 216) return;
    const int rg = tid / 3;
    const int cg = tid % 3;
    float acc[3][12];
    #pragma unroll
    for (int rr = 0; rr < 3; rr++)
        #pragma unroll
        for (int j = 0; j < 12; j++) acc[rr][j] = 0.0f;
    #pragma unroll 1
    for (int u = 0; u < 6; u++) {
        float e[3];
        #pragma unroll
        for (int rr = 0; rr < 3; rr++) e[rr] = sm[eOff + u * 216 + rg * 3 + rr];
        const float4* nb = (const float4*)(sm + nodeOff + u * 36 + cg * 12);
        float4 n0 = nb[0], n1 = nb[1], n2 = nb[2];
        #pragma unroll
        for (int rr = 0; rr < 3; rr++) {
            acc[rr][0] += e[rr] * n0.x; acc[rr][1]  += e[rr] * n0.y;
            acc[rr][2] += e[rr] * n0.z; acc[rr][3]  += e[rr] * n0.w;
            acc[rr][4] += e[rr] * n1.x; acc[rr][5]  += e[rr] * n1.y;
            acc[rr][6] += e[rr] * n1.z; acc[rr][7]  += e[rr] * n1.w;
            acc[rr][8] += e[rr] * n2.x; acc[rr][9]  += e[rr] * n2.y;
            acc[rr][10]+= e[rr] * n2.z; acc[rr][11] += e[rr] * n2.w;
        }
    }
    #pragma unroll
    for (int rr = 0; rr < 3; rr++) {
        float4* out = (float4*)(sm + outOff + (rg * 3 + rr) * 36 + cg * 12);
        out[0] = make_float4(acc[rr][0], acc[rr][1], acc[rr][2], acc[rr][3]);
        out[1] = make_float4(acc[rr][4], acc[rr][5], acc[rr][6], acc[rr][7]);
        out[2] = make_float4(acc[rr][8], acc[rr][9], acc[rr][10], acc[rr][11]);
    }
}

// out[c*36 + b] = sum_{u,x} in[u*1296 + c*6 + x] * nodeL[(u*6+x)*36 + b]
__device__ __forceinline__ void mpo_full36(int outOff, int inOff, int nodeOff, int tid)
{
    if (tid >= 216) return;
    const int rg = tid / 3;
    const int cg = tid % 3;
    float acc[3][12];
    #pragma unroll
    for (int rr = 0; rr < 3; rr++)
        #pragma unroll
        for (int j = 0; j < 12; j++) acc[rr][j] = 0.0f;
    #pragma unroll 1
    for (int u = 0; u < 6; u++) {
        float a[3][6];
        #pragma unroll
        for (int rr = 0; rr < 3; rr++) {
            const float2* sp = (const float2*)(sm + inOff + u * 1296 + (rg * 3 + rr) * 6);
            float2 s01 = sp[0], s23 = sp[1], s45 = sp[2];
            a[rr][0] = s01.x; a[rr][1] = s01.y;
            a[rr][2] = s23.x; a[rr][3] = s23.y;
            a[rr][4] = s45.x; a[rr][5] = s45.y;
        }
        #pragma unroll
        for (int x = 0; x < 6; x++) {
            const float4* nb = (const float4*)(sm + nodeOff + (u * 6 + x) * 36 + cg * 12);
            float4 n0 = nb[0], n1 = nb[1], n2 = nb[2];
            #pragma unroll
            for (int rr = 0; rr < 3; rr++) {
                float sv = a[rr][x];
                acc[rr][0] += sv * n0.x; acc[rr][1]  += sv * n0.y;
                acc[rr][2] += sv * n0.z; acc[rr][3]  += sv * n0.w;
                acc[rr][4] += sv * n1.x; acc[rr][5]  += sv * n1.y;
                acc[rr][6] += sv * n1.z; acc[rr][7]  += sv * n1.w;
                acc[rr][8] += sv * n2.x; acc[rr][9]  += sv * n2.y;
                acc[rr][10]+= sv * n2.z; acc[rr][11] += sv * n2.w;
            }
        }
    }
    #pragma unroll
    for (int rr = 0; rr < 3; rr++) {
        float4* out = (float4*)(sm + outOff + (rg * 3 + rr) * 36 + cg * 12);
        out[0] = make_float4(acc[rr][0], acc[rr][1], acc[rr][2], acc[rr][3]);
        out[1] = make_float4(acc[rr][4], acc[rr][5], acc[rr][6], acc[rr][7]);
        out[2] = make_float4(acc[rr][8], acc[rr][9], acc[rr][10], acc[rr][11]);
    }
}

// out[c*6 + d] = sum_{u,x} in[u*1296 + c*6 + x] * nodeLa[(u*6+x)*6 + d]; returns sumsq
__device__ __forceinline__ float mpo_last36_sq(int outOff, int inOff, int nodeOff, int tid)
{
    if (tid >= 216) return 0.0f;
    float acc[6] = {0, 0, 0, 0, 0, 0};
    #pragma unroll 1
    for (int u = 0; u < 6; u++) {
        const float2* sp = (const float2*)(sm + inOff + u * 1296 + tid * 6);
        float2 s01 = sp[0], s23 = sp[1], s45 = sp[2];
        float sx[6] = {s01.x, s01.y, s23.x, s23.y, s45.x, s45.y};
        #pragma unroll
        for (int x = 0; x < 6; x++) {
            float sv = sx[x];
            const float2* nb = (const float2*)(sm + nodeOff + (u * 6 + x) * 6);
            float2 n01 = nb[0], n23 = nb[1], n45 = nb[2];
            acc[0] += sv * n01.x; acc[1] += sv * n01.y;
            acc[2] += sv * n23.x; acc[3] += sv * n23.y;
            acc[4] += sv * n45.x; acc[5] += sv * n45.y;
        }
    }
    float2* out = (float2*)(sm + outOff + tid * 6);
    out[0] = make_float2(acc[0], acc[1]);
    out[1] = make_float2(acc[2], acc[3]);
    out[2] = make_float2(acc[4], acc[5]);
    float ss = 0.0f;
    #pragma unroll
    for (int i = 0; i < 6; i++) ss += acc[i] * acc[i];
    return ss;
}

// R[m*36 + d2*6 + l3] = sum_d3 EbT[d3*216 + d0d1*6 + d2] * n23[u3*36 + d3*6 + l3]
__device__ __noinline__ void rstep36(int outOff, int ebOff, int nodeOff, int tid)
{
    if (tid >= 216) return;
    int u3 = tid / 36;
    int dd = tid % 36;
    float acc[36];
    #pragma unroll
    for (int i = 0; i < 36; i++) acc[i] = 0.0f;
    #pragma unroll 1
    for (int d3 = 0; d3 < 6; d3++) {
        const float2* ep = (const float2*)(sm + ebOff + d3 * 216 + dd * 6);
        float2 e01 = ep[0], e23 = ep[1], e45 = ep[2];
        float eb[6] = {e01.x, e01.y, e23.x, e23.y, e45.x, e45.y};
        const float2* np = (const float2*)(sm + nodeOff + u3 * 36 + d3 * 6);
        float2 n01 = np[0], n23v = np[1], n45 = np[2];
        float nv[6] = {n01.x, n01.y, n23v.x, n23v.y, n45.x, n45.y};
        #pragma unroll
        for (int d2 = 0; d2 < 6; d2++)
            #pragma unroll
            for (int l3 = 0; l3 < 6; l3++)
                acc[d2 * 6 + l3] += eb[d2] * nv[l3];
    }
    float4* out = (float4*)(sm + outOff + tid * 36);
    #pragma unroll
    for (int q = 0; q < 9; q++)
        out[q] = make_float4(acc[q*4], acc[q*4+1], acc[q*4+2], acc[q*4+3]);
}

// T[u*216 + r*36 + d*6 + l] = sum_m L[u*1296 + m*6 + l] * R[m*36 + d*6 + r]
__device__ __noinline__ void tgemm_tiled(int tOff, int lOff, int rOff, int tid)
{
    if (tid >= 162) return;
    int pr = tid / 9;
    int bt = tid % 9;
    int u  = pr / 3;
    int l0 = (pr % 3) * 2;
    int b0 = bt * 4;
    float acc[8];
    #pragma unroll
    for (int i = 0; i < 8; i++) acc[i] = 0.0f;
    const float* Lp = sm + lOff + u * 1296 + l0;
    const float* Rp = sm + rOff + b0;
    #pragma unroll 4
    for (int m = 0; m < 216; m++) {
        float2 a  = *(const float2*)(Lp + m * 6);
        float4 bv = *(const float4*)(Rp + m * 36);
        acc[0] += a.x * bv.x; acc[1] += a.x * bv.y;
        acc[2] += a.x * bv.z; acc[3] += a.x * bv.w;
        acc[4] += a.y * bv.x; acc[5] += a.y * bv.y;
        acc[6] += a.y * bv.z; acc[7] += a.y * bv.w;
    }
    #pragma unroll
    for (int j = 0; j < 4; j++) {
        int beta = b0 + j;
        int d = beta / 6;
        int r = beta % 6;
        sm[tOff + u * 216 + r * 36 + d * 6 + l0]     = acc[j];
        sm[tOff + u * 216 + r * 36 + d * 6 + l0 + 1] = acc[4 + j];
    }
}

// ---------------------------------------------------------------------------
// kernel: one block per batch element, software-pipelined node loads
// ---------------------------------------------------------------------------

__global__ __launch_bounds__(NT, 3)
void peps_forward_kernel(const float* __restrict__ inputs,
                         const float* __restrict__ peps,
                         const float* __restrict__ pepsc,
                         float* __restrict__ out, int B)
{
    const int tid = threadIdx.x;
    const int b = blockIdx.x;

    if (tid < 32) sm[OFF_X + tid] = inputs[b * 32 + tid];
    __syncthreads();

    #define PB(i, j)  (peps + ((i) * 4 + (j)) * 2 * 1296)
    #define XX0(i, j) sm[OFF_X + ((i) * 4 + (j)) * 2]
    #define XX1(i, j) sm[OFF_X + ((i) * 4 + (j)) * 2 + 1]

    const int P0 = OFF_A;
    const int P1 = OFF_A + 1296;
    float vf[6];

    // ---- init: n00 [r][d] -> H0 ----
    {
        float v = pf_slice(PB(0, 0), XX0(0, 0), XX1(0, 0), 6, 1, 36, 6, 0, 36, tid);
        st_slice(H0, v, 36, tid, 1.0f);
    }
    __syncthreads();

    // ================= Row 0 =================
    // step 1: transpose n00 -> P0 ; prefetch n01 [r][d][x] -> H1
    {
        float v = pf_slice(PB(0, 1), XX0(0, 1), XX1(0, 1), 6, 6, 36, 6, 1, 216, tid);
        if (tid < 36) { int d0 = tid / 6, r = tid % 6; sm[P0 + tid] = sm[H0 + r * 6 + d0]; }
        st_slice(H1, v, 216, tid, 1.0f);
    }
    __syncthreads();
    // step 2
    {
        float v = pf_slice(PB(0, 2), XX0(0, 2), XX1(0, 2), 6, 6, 36, 6, 1, 216, tid);
        rowstep(P1, P0, H1, 6, false, tid);
        st_slice(H0, v, 216, tid, 1.0f);
    }
    __syncthreads();
    // step 3: prefetch n03 [d][x] (36)
    {
        float v = pf_slice(PB(0, 3), XX0(0, 3), XX1(0, 3), 6, 1, 6, 1, 0, 36, tid);
        rowstep(P0, P1, H0, 36, false, tid);
        st_slice(H1, v, 36, tid, 1.0f);
    }
    __syncthreads();
    // step 4: env0 (raw) -> B ; scale folded into n10 [u][d][r]
    {
        float v = pf_slice(PB(1, 0), XX0(1, 0), XX1(1, 0), 6, 6, 216, 6, 36, 216, tid);
        float ss = laststep_sq(OFF_B, P0, H1, tid);
        sumsq_publish(ss, tid);
        __syncthreads();
        float sc = read_scale();
        st_slice(H0, v, 216, tid, sc);
    }
    __syncthreads();

    // ================= Row 1 =================
    {
        pf_full(vf, PB(1, 1), XX0(1, 1), XX1(1, 1), tid);
        mpo_first36(OFF_A, OFF_B, H0, tid);
        st_full(H1, vf, tid);
    }
    __syncthreads();
    {
        pf_full(vf, PB(1, 2), XX0(1, 2), XX1(1, 2), tid);
        mpo_full36(OFF_B, OFF_A, H1, tid);
        st_full(H0, vf, tid);
    }
    __syncthreads();
    {
        float v = pf_slice(PB(1, 3), XX0(1, 3), XX1(1, 3), 6, 6, 216, 1, 6, 216, tid); // [u][x][d]
        mpo_full36(OFF_A, OFF_B, H0, tid);
        st_slice(H1, v, 216, tid, 1.0f);
    }
    __syncthreads();
    // env_top (raw) -> B ; scale folded into n20 [u][d][r]
    {
        float v = pf_slice(PB(2, 0), XX0(2, 0), XX1(2, 0), 6, 6, 216, 6, 36, 216, tid);
        float ss = mpo_last36_sq(OFF_B, OFF_A, H1, tid);
        sumsq_publish(ss, tid);
        __syncthreads();
        float sc = read_scale();
        st_slice(H0, v, 216, tid, sc);
    }
    __syncthreads();

    // ================= Row 2 L-part =================
    {
        pf_full(vf, PB(2, 1), XX0(2, 1), XX1(2, 1), tid);
        mpo_first36(OFF_A, OFF_B, H0, tid);
        st_full(H1, vf, tid);
    }
    __syncthreads();
    {
        float v = pf_slice(PB(3, 0), XX0(3, 0), XX1(3, 0), 6, 1, 216, 36, 0, 36, tid); // [u][r]
        mpo_full36(OFF_B, OFF_A, H1, tid);   // L2 -> B (persists)
        st_slice(H0, v, 36, tid, 1.0f);
    }
    __syncthreads();

    // ================= Row 3 (ping-pong in A; B holds L2) =================
    {
        float v = pf_slice(PB(3, 1), XX0(3, 1), XX1(3, 1), 6, 6, 216, 36, 1, 216, tid); // [u][r][x]
        if (tid < 36) sm[P0 + tid] = sm[H0 + tid];
        st_slice(H1, v, 216, tid, 1.0f);
    }
    __syncthreads();
    {
        float v = pf_slice(PB(3, 2), XX0(3, 2), XX1(3, 2), 6, 6, 216, 36, 1, 216, tid);
        rowstep(P1, P0, H1, 6, true, tid);
        st_slice(H0, v, 216, tid, 1.0f);
    }
    __syncthreads();
    {
        float v = pf_slice(PB(3, 3), XX0(3, 3), XX1(3, 3), 6, 1, 216, 1, 0, 36, tid);   // [u][x]
        rowstep(P0, P1, H0, 36, true, tid);
        st_slice(H0 + 432, v, 36, tid, 1.0f);   // n33 parked past n32
    }
    __syncthreads();
    // env_botT (raw) -> H1 ; scale folded into n23 [u][d][l]
    {
        float v = pf_slice(PB(2, 3), XX0(2, 3), XX1(2, 3), 6, 6, 216, 6, 1, 216, tid);
        float ss = laststep_T_sq(H1, P0, H0 + 432, tid);
        sumsq_publish(ss, tid);
        __syncthreads();
        float sc = read_scale();
        st_slice(H0, v, 216, tid, sc);
    }
    __syncthreads();

    // ================= R-part + merge =================
    rstep36(OFF_A, H1, H0, tid);          // R -> A
    __syncthreads();
    tgemm_tiled(H0, OFF_B, OFF_A, tid);   // T -> H0
    __syncthreads();

    // ================= Final contraction with peps_center ================
    {
        const float xc0 = XX0(2, 2);
        const float xc1 = XX1(2, 2);
        float acc[10];
        #pragma unroll
        for (int o = 0; o < 10; o++) acc[o] = 0.0f;
        for (int k = tid; k < 1296; k += NT) {
            float e  = sm[H0 + k];
            float e0 = e * xc0;
            float e1 = e * xc1;
            #pragma unroll
            for (int o = 0; o < 10; o++)
                acc[o] += e0 * __ldg(pepsc + o * 1296 + k)
                        + e1 * __ldg(pepsc + 12960 + o * 1296 + k);
        }
        #pragma unroll
        for (int o = 0; o < 10; o++)
            #pragma unroll
            for (int off = 16; off > 0; off >>= 1)
                acc[o] += __shfl_down_sync(0xffffffffu, acc[o], off);
        const int w = tid >> 5;
        if ((tid & 31) == 0) {
            #pragma unroll
            for (int o = 0; o < 10; o++) sm[OFF_A + w * 10 + o] = acc[o];
        }
        __syncthreads();
        if (tid < 10) {
            float s = 0.0f;
            #pragma unroll
            for (int ww = 0; ww < 7; ww++) s += sm[OFF_A + ww * 10 + tid];
            sm[OFF_OUT + tid] = s;
        }
        __syncthreads();
    }

    if (tid < 10) {
        float nrm = 0.0f;
        #pragma unroll
        for (int o = 0; o < 10; o++) { float t = sm[OFF_OUT + o]; nrm += t * t; }
        out[b * 10 + tid] = sm[OFF_OUT + tid] * rsqrtf(nrm);
    }
}

// ---------------------------------------------------------------------------
// launch
// ---------------------------------------------------------------------------

extern "C" void kernel_launch(void* const* d_in, const int* in_sizes, int n_in,
                              void* d_out, int out_size)
{
    const float* inputs = (const float*)d_in[0];   // (B,4,4,2)
    const float* peps   = (const float*)d_in[1];   // (4,4,2,6,6,6,6)
    const float* pepsc  = (const float*)d_in[2];   // (2,10,6,6,6,6)
    float* out = (float*)d_out;                    // (B,10)

    const int B = in_sizes[0] / 32;

    cudaFuncSetAttribute(peps_forward_kernel,
                         cudaFuncAttributeMaxDynamicSharedMemorySize, SMEM_BYTES);
    peps_forward_kernel<<<B, NT, SMEM_BYTES>>>(inputs, peps, pepsc, out, B);
}